// round 7
// baseline (speedup 1.0000x reference)
#include <cuda_runtime.h>

// out[n][d] = (x[n]==0 ? 0 : W[x[n]][d]) + PE(n,d)
// Even exponents e in {0,2,...,1024} -> 513 distinct frequencies (NE).
//
// setup (single launch, 525K threads, fully parallel): each thread computes
//   w = 10000^{-e/D} inline in DP (~3us chip-wide), then
//   seed[c][ie] = (sin,cos)((128c+1)*w) via DP mul + DP mod-2pi + MUFU.
//   The c==0 slice also writes the unit rotation (DP small-arg sincos).
// main (memory-clean): per 128-row chunk, 6 table loads, then gather+add+
//   store with G=8 load batching (79% DRAM). fp32 rotation per row,
//   exact reseed every 128 rows -> rel_err ~3.4e-4.

#define D_DIM   1024
#define TPB     256
#define ROWS    128
#define MAXN    131072
#define NCHUNK  (MAXN / ROWS)    // 1024
#define NE      513              // even exponents 0..1024
#define G       8                // rows batched per inner iteration

__device__ float2 g_seed[NCHUNK * NE];  // [c][ie] = (sin,cos)((128c+1)*w_e)
__device__ float2 g_rot[NE];            // [ie]    = (sin,cos)(w_e)

__global__ void pe_setup(int nchunks)
{
    int gid = blockIdx.x * blockDim.x + threadIdx.x;
    int total = nchunks * NE;
    if (gid >= total) return;
    int c  = gid / NE;
    int ie = gid - c * NE;

    const double LOG1E4  = 9.210340371976184;          // ln(10000)
    const double TWO_PI  = 6.283185307179586476925287;
    const double INV_2PI = 0.15915494309189533576888;

    double w = exp(-(double)(2 * ie) * (LOG1E4 / (double)D_DIM));  // inline, parallel

    double ang = (double)(c * ROWS + 1) * w;
    ang -= TWO_PI * floor(ang * INV_2PI);
    float ss, cc;
    __sincosf((float)ang, &ss, &cc);                   // MUFU: ~1e-6 abs
    g_seed[gid] = make_float2(ss, cc);

    if (c == 0) {                                      // 513 threads only
        double sw, cw;
        sincos(w, &sw, &cw);                           // small arg: fast path
        g_rot[ie] = make_float2((float)sw, (float)cw);
    }
}

__global__ __launch_bounds__(TPB, 3)
void pe_embed_kernel(const int* __restrict__ x,
                     const float* __restrict__ W,
                     float* __restrict__ out,
                     int N)
{
    __shared__ int sx[ROWS];

    const int chunk = blockIdx.x;
    const int n0 = chunk * ROWS;
    const int t  = threadIdx.x;

    if (t < ROWS) {
        int n = n0 + t;
        sx[t] = (n < N) ? x[n] : 0;
    }

    // states m=0..2 use exponent e = 4t + 2m -> table index ie = 2t + m
    float s[3], c[3], sw[3], cw[3];
    {
        const float2* __restrict__ seed = g_seed + (long)chunk * NE;
#pragma unroll
        for (int m = 0; m < 3; m++) {
            int ie = 2 * t + m;
            float2 sc = __ldg(&seed[ie]);
            float2 rt = __ldg(&g_rot[ie]);
            s[m] = sc.x;  c[m] = sc.y;
            sw[m] = rt.x; cw[m] = rt.y;
        }
    }
    __syncthreads();

    const float4* __restrict__ Wv = (const float4*)W;
    float4* outv = (float4*)out;

    const int nr = (N - n0 < ROWS) ? (N - n0) : ROWS;
    const long obase = (long)n0 * (D_DIM / 4) + t;

    if (nr == ROWS) {
        // fast path: batch G row-gathers before compute/store -> deep MLP
        for (int rb = 0; rb < ROWS; rb += G) {
            int    idx[G];
            float4 e[G];
#pragma unroll
            for (int j = 0; j < G; j++) idx[j] = sx[rb + j];
#pragma unroll
            for (int j = 0; j < G; j++)   // unconditional: row 0 is valid memory
                e[j] = __ldg(&Wv[(long)idx[j] * (D_DIM / 4) + t]);
#pragma unroll
            for (int j = 0; j < G; j++) {
                float msk = (idx[j] == 0) ? 0.f : 1.f;   // padding row -> zero
                float4 o;
                o.x = fmaf(e[j].x, msk, c[0]);
                o.y = fmaf(e[j].y, msk, s[1]);
                o.z = fmaf(e[j].z, msk, c[1]);
                o.w = fmaf(e[j].w, msk, s[2]);
                __stcs(&outv[obase + (long)(rb + j) * (D_DIM / 4)], o);
#pragma unroll
                for (int m = 0; m < 3; m++) {
                    float ns = fmaf(s[m], cw[m],  c[m] * sw[m]);
                    float nc = fmaf(c[m], cw[m], -s[m] * sw[m]);
                    s[m] = ns; c[m] = nc;
                }
            }
        }
    } else {
        for (int r = 0; r < nr; r++) {
            int idx = sx[r];
            float4 e = make_float4(0.f, 0.f, 0.f, 0.f);
            if (idx != 0) e = __ldg(&Wv[(long)idx * (D_DIM / 4) + t]);
            float4 o;
            o.x = e.x + c[0];
            o.y = e.y + s[1];
            o.z = e.z + c[1];
            o.w = e.w + s[2];
            __stcs(&outv[obase + (long)r * (D_DIM / 4)], o);
#pragma unroll
            for (int m = 0; m < 3; m++) {
                float ns = fmaf(s[m], cw[m],  c[m] * sw[m]);
                float nc = fmaf(c[m], cw[m], -s[m] * sw[m]);
                s[m] = ns; c[m] = nc;
            }
        }
    }
}

extern "C" void kernel_launch(void* const* d_in, const int* in_sizes, int n_in,
                              void* d_out, int out_size)
{
    const int*   x;
    const float* W;
    int N;
    if (in_sizes[0] < in_sizes[1]) {
        x = (const int*)d_in[0];  W = (const float*)d_in[1];  N = in_sizes[0];
    } else {
        x = (const int*)d_in[1];  W = (const float*)d_in[0];  N = in_sizes[1];
    }
    int nchunks = (N + ROWS - 1) / ROWS;
    if (nchunks > NCHUNK) nchunks = NCHUNK;

    int total = nchunks * NE;
    pe_setup<<<(total + 255) / 256, 256>>>(nchunks);

    pe_embed_kernel<<<nchunks, TPB>>>(x, W, (float*)d_out, N);
}

// round 8
// speedup vs baseline: 1.0943x; 1.0943x over previous
#include <cuda_runtime.h>

// out[n][d] = (x[n]==0 ? 0 : W[x[n]][d]) + PE(n,d)
// Even exponents e in {0,2,...,1024} -> 513 distinct frequencies (NE).
// w_e = 10000^{-e/1024} = r^{ie},  r = 10000^{-1/512},  ie = e/2.
// w is reconstructed at runtime as A[ie>>5] * B[ie&31] where A,B are
// COMPILE-TIME constexpr tables (no runtime DP exp anywhere).
//
// setup (1 launch, 525K thr): seed[c][ie] = (sin,cos)((128c+1)*w) via
//   DMUL + DP mod-2pi + MUFU __sincosf. Store-bound, ~3us.
// main (memory-clean): per 128-row chunk, 6 table loads, G=8 batched
//   gathers (79% DRAM), fp32 rotation per row, exact reseed per chunk.

#define D_DIM   1024
#define TPB     256
#define ROWS    128
#define MAXN    131072
#define NCHUNK  (MAXN / ROWS)    // 1024
#define NE      513              // even exponents 0..1024
#define G       8                // rows batched per inner iteration

// ---- compile-time construction of r^k tables ----
constexpr double cexp_small(double x) {   // |x| < 0.02: Taylor, full DP precision
    double t = 1.0, term = 1.0;
    for (int i = 1; i < 22; i++) { term *= x / (double)i; t += term; }
    return t;
}
constexpr double cpow_u(double base, int n) {  // binary exponentiation
    double acc = 1.0, b = base;
    while (n) { if (n & 1) acc *= b; b *= b; n >>= 1; }
    return acc;
}
constexpr double R_STEP = cexp_small(-9.210340371976184 / 512.0);  // 10000^{-1/512}

#define PA(k) cpow_u(R_STEP, 32 * (k))
#define PB(k) cpow_u(R_STEP, (k))
__constant__ double c_A[17] = {
    PA(0),  PA(1),  PA(2),  PA(3),  PA(4),  PA(5),  PA(6),  PA(7),
    PA(8),  PA(9),  PA(10), PA(11), PA(12), PA(13), PA(14), PA(15), PA(16)
};
__constant__ double c_B[32] = {
    PB(0),  PB(1),  PB(2),  PB(3),  PB(4),  PB(5),  PB(6),  PB(7),
    PB(8),  PB(9),  PB(10), PB(11), PB(12), PB(13), PB(14), PB(15),
    PB(16), PB(17), PB(18), PB(19), PB(20), PB(21), PB(22), PB(23),
    PB(24), PB(25), PB(26), PB(27), PB(28), PB(29), PB(30), PB(31)
};

__device__ float2 g_seed[NCHUNK * NE];  // [c][ie] = (sin,cos)((128c+1)*w_e)
__device__ float2 g_rot[NE];            // [ie]    = (sin,cos)(w_e)

__global__ void pe_setup(int nchunks)
{
    int gid = blockIdx.x * blockDim.x + threadIdx.x;
    int total = nchunks * NE;
    if (gid >= total) return;
    int c  = gid / NE;
    int ie = gid - c * NE;

    const double TWO_PI  = 6.283185307179586476925287;
    const double INV_2PI = 0.15915494309189533576888;

    double w = c_A[ie >> 5] * c_B[ie & 31];       // exact to ~1e-15 rel

    double ang = (double)(c * ROWS + 1) * w;
    ang -= TWO_PI * floor(ang * INV_2PI);
    float ss, cc;
    __sincosf((float)ang, &ss, &cc);              // MUFU: ~1e-6 abs
    g_seed[gid] = make_float2(ss, cc);

    if (c == 0) {                                 // 513 threads, latency hidden
        double sw, cw;
        sincos(w, &sw, &cw);                      // small arg: fast path
        g_rot[ie] = make_float2((float)sw, (float)cw);
    }
}

__global__ __launch_bounds__(TPB, 3)
void pe_embed_kernel(const int* __restrict__ x,
                     const float* __restrict__ W,
                     float* __restrict__ out,
                     int N)
{
    __shared__ int sx[ROWS];

    const int chunk = blockIdx.x;
    const int n0 = chunk * ROWS;
    const int t  = threadIdx.x;

    if (t < ROWS) {
        int n = n0 + t;
        sx[t] = (n < N) ? x[n] : 0;
    }

    // states m=0..2 use exponent e = 4t + 2m -> table index ie = 2t + m
    float s[3], c[3], sw[3], cw[3];
    {
        const float2* __restrict__ seed = g_seed + (long)chunk * NE;
#pragma unroll
        for (int m = 0; m < 3; m++) {
            int ie = 2 * t + m;
            float2 sc = __ldg(&seed[ie]);
            float2 rt = __ldg(&g_rot[ie]);
            s[m] = sc.x;  c[m] = sc.y;
            sw[m] = rt.x; cw[m] = rt.y;
        }
    }
    __syncthreads();

    const float4* __restrict__ Wv = (const float4*)W;
    float4* outv = (float4*)out;

    const int nr = (N - n0 < ROWS) ? (N - n0) : ROWS;
    const long obase = (long)n0 * (D_DIM / 4) + t;

    if (nr == ROWS) {
        // fast path: batch G row-gathers before compute/store -> deep MLP
        for (int rb = 0; rb < ROWS; rb += G) {
            int    idx[G];
            float4 e[G];
#pragma unroll
            for (int j = 0; j < G; j++) idx[j] = sx[rb + j];
#pragma unroll
            for (int j = 0; j < G; j++)   // unconditional: row 0 is valid memory
                e[j] = __ldg(&Wv[(long)idx[j] * (D_DIM / 4) + t]);
#pragma unroll
            for (int j = 0; j < G; j++) {
                float msk = (idx[j] == 0) ? 0.f : 1.f;   // padding row -> zero
                float4 o;
                o.x = fmaf(e[j].x, msk, c[0]);
                o.y = fmaf(e[j].y, msk, s[1]);
                o.z = fmaf(e[j].z, msk, c[1]);
                o.w = fmaf(e[j].w, msk, s[2]);
                __stcs(&outv[obase + (long)(rb + j) * (D_DIM / 4)], o);
#pragma unroll
                for (int m = 0; m < 3; m++) {
                    float ns = fmaf(s[m], cw[m],  c[m] * sw[m]);
                    float nc = fmaf(c[m], cw[m], -s[m] * sw[m]);
                    s[m] = ns; c[m] = nc;
                }
            }
        }
    } else {
        for (int r = 0; r < nr; r++) {
            int idx = sx[r];
            float4 e = make_float4(0.f, 0.f, 0.f, 0.f);
            if (idx != 0) e = __ldg(&Wv[(long)idx * (D_DIM / 4) + t]);
            float4 o;
            o.x = e.x + c[0];
            o.y = e.y + s[1];
            o.z = e.z + c[1];
            o.w = e.w + s[2];
            __stcs(&outv[obase + (long)r * (D_DIM / 4)], o);
#pragma unroll
            for (int m = 0; m < 3; m++) {
                float ns = fmaf(s[m], cw[m],  c[m] * sw[m]);
                float nc = fmaf(c[m], cw[m], -s[m] * sw[m]);
                s[m] = ns; c[m] = nc;
            }
        }
    }
}

extern "C" void kernel_launch(void* const* d_in, const int* in_sizes, int n_in,
                              void* d_out, int out_size)
{
    const int*   x;
    const float* W;
    int N;
    if (in_sizes[0] < in_sizes[1]) {
        x = (const int*)d_in[0];  W = (const float*)d_in[1];  N = in_sizes[0];
    } else {
        x = (const int*)d_in[1];  W = (const float*)d_in[0];  N = in_sizes[1];
    }
    int nchunks = (N + ROWS - 1) / ROWS;
    if (nchunks > NCHUNK) nchunks = NCHUNK;

    int total = nchunks * NE;
    pe_setup<<<(total + 255) / 256, 256>>>(nchunks);

    pe_embed_kernel<<<nchunks, TPB>>>(x, W, (float*)d_out, N);
}

// round 10
// speedup vs baseline: 1.1689x; 1.0682x over previous
#include <cuda_runtime.h>

// Single fused kernel, zero FP64 at runtime.
// out[n][d] = (x[n]==0 ? 0 : W[x[n]][d]) + PE(n,d)
// Even exponents e in {0,...,1024}: w_e = r^{ie}, r = 10000^{-1/512}, ie=e/2.
// w stored as a COMPILE-TIME two-float (hi,lo) table; seed angle
// (n0+1)*w mod 2pi computed in fp32 error-free-transform + Cody-Waite,
// then MUFU __sincosf. Rotation constants also via MUFU (error*128 ~2.5e-5).
// Hot loop unchanged from the 143.5us/79.8%-DRAM kernel: G=8 batched gathers,
// fp32 rotation recurrence, exact reseed every 128 rows.

#define D_DIM   1024
#define TPB     256
#define ROWS    128
#define G       8

// ---- compile-time construction of w = r^k as two-float ----
constexpr double cexp_small(double x) {       // |x|<0.02: Taylor, full DP prec
    double t = 1.0, term = 1.0;
    for (int i = 1; i < 22; i++) { term *= x / (double)i; t += term; }
    return t;
}
constexpr double cpow_u(double base, int n) { // binary exponentiation
    double acc = 1.0, b = base;
    while (n) { if (n & 1) acc *= b; b *= b; n >>= 1; }
    return acc;
}
constexpr double R_STEP = cexp_small(-9.210340371976184 / 512.0); // 10000^{-1/512}

#define CW(k)  cpow_u(R_STEP, (k))
#define WHI(k) ((float)CW(k))
#define WLO(k) ((float)(CW(k) - (double)((float)CW(k))))
#define W2(k)  { WHI(k), WLO(k) }
#define W2R(b) W2(b+0),W2(b+1),W2(b+2),W2(b+3),W2(b+4),W2(b+5),W2(b+6),W2(b+7), \
               W2(b+8),W2(b+9),W2(b+10),W2(b+11),W2(b+12),W2(b+13),W2(b+14),W2(b+15), \
               W2(b+16),W2(b+17),W2(b+18),W2(b+19),W2(b+20),W2(b+21),W2(b+22),W2(b+23), \
               W2(b+24),W2(b+25),W2(b+26),W2(b+27),W2(b+28),W2(b+29),W2(b+30),W2(b+31)

__device__ const float2 g_w2[513] = {
    W2R(0),   W2R(32),  W2R(64),  W2R(96),  W2R(128), W2R(160), W2R(192), W2R(224),
    W2R(256), W2R(288), W2R(320), W2R(352), W2R(384), W2R(416), W2R(448), W2R(480),
    W2(512)
};

__global__ __launch_bounds__(TPB, 3)
void pe_embed_fused(const int* __restrict__ x,
                    const float* __restrict__ W,
                    float* __restrict__ out,
                    int N)
{
    __shared__ int sx[ROWS];

    const int chunk = blockIdx.x;
    const int n0 = chunk * ROWS;
    const int t  = threadIdx.x;

    if (t < ROWS) {
        int n = n0 + t;
        sx[t] = (n < N) ? x[n] : 0;
    }

    // states m=0..2 use exponent e = 4t+2m -> table index ie = 2t+m
    float s[3], c[3], sw[3], cw[3];
    {
        const float INV_2PI = 0.15915494309189535f;
        const float C1 = 6.28125f;                 // 201/32: k*C1 exact for k<2^15
        const float C2 = 1.9353071795864770e-3f;   // 2pi - C1  (FIXED constant)
        const float p  = (float)(n0 + 1);          // exact: < 2^17
#pragma unroll
        for (int m = 0; m < 3; m++) {
            int ie = 2 * t + m;
            float2 wv = __ldg(&g_w2[ie]);
            // two-float product p*w
            float hi  = p * wv.x;
            float err = fmaf(p, wv.x, -hi);        // exact residual
            float lo  = fmaf(p, wv.y, err);
            // Cody-Waite mod 2pi
            float k = rintf(hi * INV_2PI);
            float r = fmaf(-k, C1, hi);
            r = fmaf(-k, C2, r);
            r += lo;
            __sincosf(r, &s[m], &c[m]);
            // per-row rotation constants
            float w1 = wv.x + wv.y;
            __sincosf(w1, &sw[m], &cw[m]);
        }
    }
    __syncthreads();

    const float4* __restrict__ Wv = (const float4*)W;
    float4* outv = (float4*)out;

    const int nr = (N - n0 < ROWS) ? (N - n0) : ROWS;
    const long obase = (long)n0 * (D_DIM / 4) + t;

    if (nr == ROWS) {
        // fast path: batch G row-gathers before compute/store -> deep MLP
        for (int rb = 0; rb < ROWS; rb += G) {
            int    idx[G];
            float4 e[G];
#pragma unroll
            for (int j = 0; j < G; j++) idx[j] = sx[rb + j];
#pragma unroll
            for (int j = 0; j < G; j++)   // unconditional: row 0 is valid memory
                e[j] = __ldg(&Wv[(long)idx[j] * (D_DIM / 4) + t]);
#pragma unroll
            for (int j = 0; j < G; j++) {
                float msk = (idx[j] == 0) ? 0.f : 1.f;   // padding row -> zero
                float4 o;
                o.x = fmaf(e[j].x, msk, c[0]);
                o.y = fmaf(e[j].y, msk, s[1]);
                o.z = fmaf(e[j].z, msk, c[1]);
                o.w = fmaf(e[j].w, msk, s[2]);
                __stcs(&outv[obase + (long)(rb + j) * (D_DIM / 4)], o);
#pragma unroll
                for (int m = 0; m < 3; m++) {
                    float ns = fmaf(s[m], cw[m],  c[m] * sw[m]);
                    float nc = fmaf(c[m], cw[m], -s[m] * sw[m]);
                    s[m] = ns; c[m] = nc;
                }
            }
        }
    } else {
        for (int r = 0; r < nr; r++) {
            int idx = sx[r];
            float4 e = make_float4(0.f, 0.f, 0.f, 0.f);
            if (idx != 0) e = __ldg(&Wv[(long)idx * (D_DIM / 4) + t]);
            float4 o;
            o.x = e.x + c[0];
            o.y = e.y + s[1];
            o.z = e.z + c[1];
            o.w = e.w + s[2];
            __stcs(&outv[obase + (long)r * (D_DIM / 4)], o);
#pragma unroll
            for (int m = 0; m < 3; m++) {
                float ns = fmaf(s[m], cw[m],  c[m] * sw[m]);
                float nc = fmaf(c[m], cw[m], -s[m] * sw[m]);
                s[m] = ns; c[m] = nc;
            }
        }
    }
}

extern "C" void kernel_launch(void* const* d_in, const int* in_sizes, int n_in,
                              void* d_out, int out_size)
{
    const int*   x;
    const float* W;
    int N;
    if (in_sizes[0] < in_sizes[1]) {
        x = (const int*)d_in[0];  W = (const float*)d_in[1];  N = in_sizes[0];
    } else {
        x = (const int*)d_in[1];  W = (const float*)d_in[0];  N = in_sizes[1];
    }
    int nchunks = (N + ROWS - 1) / ROWS;
    pe_embed_fused<<<nchunks, TPB>>>(x, W, (float*)d_out, N);
}

// round 12
// speedup vs baseline: 1.1769x; 1.0068x over previous
#include <cuda_runtime.h>

// Single fused kernel, zero FP64 at runtime.
// out[n][d] = (x[n]==0 ? 0 : W[x[n]][d]) + PE(n,d)
// Seed path: compile-time two-float w table + fp32 EFT + Cody-Waite + MUFU.
// Hot loop: G=8 batched gathers with createpolicy/L2::evict_last cache-hint
// on W (keep gather rows resident against the streaming output),
// evict-first streaming stores, fp32 rotation recurrence, exact reseed
// every 128 rows.

#define D_DIM   1024
#define TPB     256
#define ROWS    128
#define G       8

// ---- compile-time construction of w = r^k as two-float ----
constexpr double cexp_small(double x) {       // |x|<0.02: Taylor, full DP prec
    double t = 1.0, term = 1.0;
    for (int i = 1; i < 22; i++) { term *= x / (double)i; t += term; }
    return t;
}
constexpr double cpow_u(double base, int n) { // binary exponentiation
    double acc = 1.0, b = base;
    while (n) { if (n & 1) acc *= b; b *= b; n >>= 1; }
    return acc;
}
constexpr double R_STEP = cexp_small(-9.210340371976184 / 512.0); // 10000^{-1/512}

#define CW(k)  cpow_u(R_STEP, (k))
#define WHI(k) ((float)CW(k))
#define WLO(k) ((float)(CW(k) - (double)((float)CW(k))))
#define W2(k)  { WHI(k), WLO(k) }
#define W2R(b) W2(b+0),W2(b+1),W2(b+2),W2(b+3),W2(b+4),W2(b+5),W2(b+6),W2(b+7), \
               W2(b+8),W2(b+9),W2(b+10),W2(b+11),W2(b+12),W2(b+13),W2(b+14),W2(b+15), \
               W2(b+16),W2(b+17),W2(b+18),W2(b+19),W2(b+20),W2(b+21),W2(b+22),W2(b+23), \
               W2(b+24),W2(b+25),W2(b+26),W2(b+27),W2(b+28),W2(b+29),W2(b+30),W2(b+31)

__device__ const float2 g_w2[513] = {
    W2R(0),   W2R(32),  W2R(64),  W2R(96),  W2R(128), W2R(160), W2R(192), W2R(224),
    W2R(256), W2R(288), W2R(320), W2R(352), W2R(384), W2R(416), W2R(448), W2R(480),
    W2(512)
};

// gather load with L2 evict-last priority via cache-hint policy descriptor
__device__ __forceinline__ float4 ldg_el(const float4* p, unsigned long long pol) {
    float4 v;
    asm volatile("ld.global.nc.L2::cache_hint.v4.f32 {%0,%1,%2,%3}, [%4], %5;"
                 : "=f"(v.x), "=f"(v.y), "=f"(v.z), "=f"(v.w)
                 : "l"(p), "l"(pol));
    return v;
}

__global__ __launch_bounds__(TPB, 3)
void pe_embed_fused(const int* __restrict__ x,
                    const float* __restrict__ W,
                    float* __restrict__ out,
                    int N)
{
    __shared__ int sx[ROWS];

    const int chunk = blockIdx.x;
    const int n0 = chunk * ROWS;
    const int t  = threadIdx.x;

    if (t < ROWS) {
        int n = n0 + t;
        sx[t] = (n < N) ? x[n] : 0;
    }

    // L2 evict-last policy descriptor (per-thread, built once)
    unsigned long long pol;
    asm("createpolicy.fractional.L2::evict_last.b64 %0, 1.0;" : "=l"(pol));

    // states m=0..2 use exponent e = 4t+2m -> table index ie = 2t+m
    float s[3], c[3], sw[3], cw[3];
    {
        const float INV_2PI = 0.15915494309189535f;
        const float C1 = 6.28125f;                 // 201/32: k*C1 exact for k<2^15
        const float C2 = 1.9353071795864770e-3f;   // 2pi - C1
        const float p  = (float)(n0 + 1);          // exact: < 2^17
#pragma unroll
        for (int m = 0; m < 3; m++) {
            int ie = 2 * t + m;
            float2 wv = __ldg(&g_w2[ie]);
            // two-float product p*w
            float hi  = p * wv.x;
            float err = fmaf(p, wv.x, -hi);        // exact residual
            float lo  = fmaf(p, wv.y, err);
            // Cody-Waite mod 2pi
            float k = rintf(hi * INV_2PI);
            float r = fmaf(-k, C1, hi);
            r = fmaf(-k, C2, r);
            r += lo;
            __sincosf(r, &s[m], &c[m]);
            // per-row rotation constants
            float w1 = wv.x + wv.y;
            __sincosf(w1, &sw[m], &cw[m]);
        }
    }
    __syncthreads();

    const float4* __restrict__ Wv = (const float4*)W;
    float4* outv = (float4*)out;

    const int nr = (N - n0 < ROWS) ? (N - n0) : ROWS;
    const long obase = (long)n0 * (D_DIM / 4) + t;

    if (nr == ROWS) {
        // fast path: batch G row-gathers before compute/store -> deep MLP
        for (int rb = 0; rb < ROWS; rb += G) {
            int    idx[G];
            float4 e[G];
#pragma unroll
            for (int j = 0; j < G; j++) idx[j] = sx[rb + j];
#pragma unroll
            for (int j = 0; j < G; j++)   // unconditional: row 0 is valid memory
                e[j] = ldg_el(&Wv[(long)idx[j] * (D_DIM / 4) + t], pol);
#pragma unroll
            for (int j = 0; j < G; j++) {
                float msk = (idx[j] == 0) ? 0.f : 1.f;   // padding row -> zero
                float4 o;
                o.x = fmaf(e[j].x, msk, c[0]);
                o.y = fmaf(e[j].y, msk, s[1]);
                o.z = fmaf(e[j].z, msk, c[1]);
                o.w = fmaf(e[j].w, msk, s[2]);
                __stcs(&outv[obase + (long)(rb + j) * (D_DIM / 4)], o);
#pragma unroll
                for (int m = 0; m < 3; m++) {
                    float ns = fmaf(s[m], cw[m],  c[m] * sw[m]);
                    float nc = fmaf(c[m], cw[m], -s[m] * sw[m]);
                    s[m] = ns; c[m] = nc;
                }
            }
        }
    } else {
        for (int r = 0; r < nr; r++) {
            int idx = sx[r];
            float4 e = make_float4(0.f, 0.f, 0.f, 0.f);
            if (idx != 0) e = ldg_el(&Wv[(long)idx * (D_DIM / 4) + t], pol);
            float4 o;
            o.x = e.x + c[0];
            o.y = e.y + s[1];
            o.z = e.z + c[1];
            o.w = e.w + s[2];
            __stcs(&outv[obase + (long)r * (D_DIM / 4)], o);
#pragma unroll
            for (int m = 0; m < 3; m++) {
                float ns = fmaf(s[m], cw[m],  c[m] * sw[m]);
                float nc = fmaf(c[m], cw[m], -s[m] * sw[m]);
                s[m] = ns; c[m] = nc;
            }
        }
    }
}

extern "C" void kernel_launch(void* const* d_in, const int* in_sizes, int n_in,
                              void* d_out, int out_size)
{
    const int*   x;
    const float* W;
    int N;
    if (in_sizes[0] < in_sizes[1]) {
        x = (const int*)d_in[0];  W = (const float*)d_in[1];  N = in_sizes[0];
    } else {
        x = (const int*)d_in[1];  W = (const float*)d_in[0];  N = in_sizes[1];
    }
    int nchunks = (N + ROWS - 1) / ROWS;
    pe_embed_fused<<<nchunks, TPB>>>(x, W, (float*)d_out, N);
}